// round 6
// baseline (speedup 1.0000x reference)
#include <cuda_runtime.h>
#include <cuda_bf16.h>
#include <math.h>
#include <cstdint>

// ---------------------------------------------------------------------------
// Problem constants
// ---------------------------------------------------------------------------
#define B  4
#define S  4096
#define H  1024
#define NH 16
#define D  64
#define SCALE 0.125f

#define GM (B*S)   // 16384
#define GN H       // 1024
#define GK H       // 1024

#define CTX_ELEMS ((size_t)B * S * H)

// ---------------------------------------------------------------------------
// Device scratch (allocation-free)
// ---------------------------------------------------------------------------
__device__ float g_q[B * S * H];
__device__ float g_k[B * S * H];
__device__ float g_v[B * S * H];

__device__ __nv_bfloat16 g_ah[(size_t)GM * GK];
__device__ __nv_bfloat16 g_al[(size_t)GM * GK];
__device__ __nv_bfloat16 g_wh[3][(size_t)GN * GK];
__device__ __nv_bfloat16 g_wl[3][(size_t)GN * GK];

#define GCH 8
__device__ float g_pmax[B * NH][GCH];
__device__ float g_psum[B * NH][GCH];
__device__ float g_pvac[B * NH][GCH][D];

// ---------------------------------------------------------------------------
// Helpers
// ---------------------------------------------------------------------------
__device__ __forceinline__ uint32_t smem_u32(const void* p) {
    uint32_t a;
    asm("{ .reg .u64 t; cvta.to.shared.u64 t, %1; cvt.u32.u64 %0, t; }"
        : "=r"(a) : "l"(p));
    return a;
}

__device__ __forceinline__ void cp16(uint32_t dst, const void* src) {
    asm volatile("cp.async.cg.shared.global [%0], [%1], 16;"
                 :: "r"(dst), "l"(src));
}
#define CP_COMMIT() asm volatile("cp.async.commit_group;" ::: "memory")
#define CP_WAIT0()  asm volatile("cp.async.wait_group 0;" ::: "memory")

__device__ __forceinline__ void ldsm4(uint32_t* r, uint32_t addr) {
    asm volatile("ldmatrix.sync.aligned.m8n8.x4.shared.b16 {%0,%1,%2,%3}, [%4];"
                 : "=r"(r[0]), "=r"(r[1]), "=r"(r[2]), "=r"(r[3]) : "r"(addr));
}

__device__ __forceinline__ void mma16816(float* c, const uint32_t* a,
                                         uint32_t b0, uint32_t b1) {
    asm volatile(
        "mma.sync.aligned.m16n8k16.row.col.f32.bf16.bf16.f32 "
        "{%0,%1,%2,%3}, {%4,%5,%6,%7}, {%8,%9}, {%0,%1,%2,%3};"
        : "+f"(c[0]), "+f"(c[1]), "+f"(c[2]), "+f"(c[3])
        : "r"(a[0]), "r"(a[1]), "r"(a[2]), "r"(a[3]), "r"(b0), "r"(b1));
}

// ---------------------------------------------------------------------------
// Unified split: hidden + Wq + Wk + Wv -> bf16 hi/lo, one launch.
// ---------------------------------------------------------------------------
#define HN8 ((GM * GK) / 8)
#define WN8 ((GN * GK) / 8)
#define TOTN8 (HN8 + 3 * WN8)

__global__ __launch_bounds__(256) void split_all(
    const float* __restrict__ hidden,
    const float* __restrict__ Wq,
    const float* __restrict__ Wk,
    const float* __restrict__ Wv)
{
    int i = blockIdx.x * blockDim.x + threadIdx.x;
    if (i >= TOTN8) return;

    const float* src;
    __nv_bfloat16 *hi, *lo;
    size_t off;
    if (i < HN8) {
        src = hidden; hi = g_ah; lo = g_al; off = (size_t)i * 8;
    } else {
        int j = i - HN8;
        int w = j / WN8;
        off = (size_t)(j - w * WN8) * 8;
        src = (w == 0) ? Wq : (w == 1) ? Wk : Wv;
        hi = g_wh[w]; lo = g_wl[w];
    }

    const float4* xp = (const float4*)(src + off);
    float4 a = xp[0], b = xp[1];
    float f[8] = {a.x, a.y, a.z, a.w, b.x, b.y, b.z, b.w};
    __align__(16) __nv_bfloat16 h[8];
    __align__(16) __nv_bfloat16 l[8];
    #pragma unroll
    for (int j = 0; j < 8; j++) {
        h[j] = __float2bfloat16(f[j]);
        l[j] = __float2bfloat16(f[j] - __bfloat162float(h[j]));
    }
    *(uint4*)(hi + off) = *(uint4*)h;
    *(uint4*)(lo + off) = *(uint4*)l;
}

// ---------------------------------------------------------------------------
// Persistent QKV GEMM via mma.sync, 3-term bf16 split, fp32 accum.
// 148 CTAs loop over 1536 tiles of 256(M) x 128(N); K-chunk 64, 2-stage.
// ---------------------------------------------------------------------------
#define TM 256
#define TN 128
#define TK 64
#define NCHUNK (GK / TK)                 // 16
#define AT_B  (TM * TK * 2)              // 32768
#define BT_B  (TN * TK * 2)              // 16384
#define STAGE_B (2 * AT_B + 2 * BT_B)    // 98304
#define OFF_AH 0
#define OFF_AL AT_B
#define OFF_BH (2 * AT_B)
#define OFF_BL (2 * AT_B + BT_B)
#define GSMEM  (2 * STAGE_B)             // 196608
#define NTILES ((GM / TM) * (GN / TN) * 3)   // 1536
#define GEMM_CTAS 148

__global__ __launch_bounds__(256, 1) void qkv_gemm_mma(
    const float* __restrict__ bias_q,
    const float* __restrict__ bias_k,
    const float* __restrict__ bias_v)
{
    extern __shared__ __align__(1024) char sb[];

    const int tid  = threadIdx.x;
    const int wid  = tid >> 5;
    const int lane = tid & 31;
    const int wm   = (wid >> 1) * 64;
    const int wn   = (wid & 1) * 64;

    const uint32_t sbase = smem_u32(sb);

    const int a_row_l = lane & 15;
    const int a_kb_l  = (lane >> 4) << 4;
    const int b_row_l = (lane & 7) + ((lane >> 4) << 3);
    const int b_kb_l  = ((lane >> 3) & 1) << 4;

    for (int t = blockIdx.x; t < NTILES; t += GEMM_CTAS) {
        const int z  = t >> 9;               // /512
        const int r  = t & 511;
        const int bm = (r >> 3) * TM;
        const int bn = (r & 7) * TN;

        const __nv_bfloat16* Ah = g_ah;
        const __nv_bfloat16* Al = g_al;
        const __nv_bfloat16* Bh = g_wh[z];
        const __nv_bfloat16* Bl = g_wl[z];
        const float* bias = (z == 0) ? bias_q : (z == 1) ? bias_k : bias_v;
        float* Cout = (z == 0) ? g_q : (z == 1) ? g_k : g_v;

        auto load_chunk = [&](int c, int buf) {
            const int kc = c * TK;
            const uint32_t stage = sbase + buf * STAGE_B;
            #pragma unroll
            for (int half = 0; half < 2; half++) {
                const __nv_bfloat16* src = half ? Al : Ah;
                uint32_t dtile = stage + (half ? OFF_AL : OFF_AH);
                #pragma unroll
                for (int i = 0; i < 8; i++) {
                    int idx = tid + i * 256;
                    int row = idx >> 3;
                    int v   = idx & 7;
                    uint32_t off = (uint32_t)(row << 7) + (uint32_t)(v << 4);
                    off ^= ((uint32_t)(row & 7) << 4);
                    cp16(dtile + off, src + (size_t)(bm + row) * GK + kc + v * 8);
                }
            }
            #pragma unroll
            for (int half = 0; half < 2; half++) {
                const __nv_bfloat16* src = half ? Bl : Bh;
                uint32_t dtile = stage + (half ? OFF_BL : OFF_BH);
                #pragma unroll
                for (int i = 0; i < 4; i++) {
                    int idx = tid + i * 256;
                    int row = idx >> 3;
                    int v   = idx & 7;
                    uint32_t off = (uint32_t)(row << 7) + (uint32_t)(v << 4);
                    off ^= ((uint32_t)(row & 7) << 4);
                    cp16(dtile + off, src + (size_t)(bn + row) * GK + kc + v * 8);
                }
            }
        };

        float acc[4][8][4];
        #pragma unroll
        for (int f = 0; f < 4; f++)
            #pragma unroll
            for (int g = 0; g < 8; g++)
                #pragma unroll
                for (int j = 0; j < 4; j++) acc[f][g][j] = 0.f;

        // safe across tiles: buf0 readers (compute c=14) are past the c=15 sync
        load_chunk(0, 0);
        CP_COMMIT();

        for (int c = 0; c < NCHUNK; c++) {
            const int buf = c & 1;
            CP_WAIT0();
            __syncthreads();
            if (c + 1 < NCHUNK) {
                load_chunk(c + 1, buf ^ 1);
                CP_COMMIT();
            }

            const uint32_t stage  = sbase + buf * STAGE_B;
            const uint32_t baseAh = stage + OFF_AH;
            const uint32_t baseAl = stage + OFF_AL;
            const uint32_t baseBh = stage + OFF_BH;
            const uint32_t baseBl = stage + OFF_BL;

            #pragma unroll
            for (int s = 0; s < 4; s++) {
                uint32_t aH[4][4], aL[4][4], bH[4][4], bL[4][4];
                const uint32_t cbA = (uint32_t)(s * 32 + a_kb_l);
                const uint32_t cbB = (uint32_t)(s * 32 + b_kb_l);
                #pragma unroll
                for (int f = 0; f < 4; f++) {
                    int row = wm + f * 16 + a_row_l;
                    uint32_t off = (uint32_t)(row << 7) + (cbA ^ ((uint32_t)(row & 7) << 4));
                    ldsm4(aH[f], baseAh + off);
                    ldsm4(aL[f], baseAl + off);
                }
                #pragma unroll
                for (int g16 = 0; g16 < 4; g16++) {
                    int row = wn + g16 * 16 + b_row_l;
                    uint32_t off = (uint32_t)(row << 7) + (cbB ^ ((uint32_t)(row & 7) << 4));
                    ldsm4(bH[g16], baseBh + off);
                    ldsm4(bL[g16], baseBl + off);
                }
                #pragma unroll
                for (int f = 0; f < 4; f++) {
                    #pragma unroll
                    for (int g16 = 0; g16 < 4; g16++) {
                        #pragma unroll
                        for (int p = 0; p < 2; p++) {
                            float* cc = acc[f][g16 * 2 + p];
                            mma16816(cc, aH[f], bH[g16][2*p], bH[g16][2*p+1]);
                            mma16816(cc, aH[f], bL[g16][2*p], bL[g16][2*p+1]);
                            mma16816(cc, aL[f], bH[g16][2*p], bH[g16][2*p+1]);
                        }
                    }
                }
            }
        }

        // epilogue: bias + fp32 store (registers only; no smem use)
        #pragma unroll
        for (int f = 0; f < 4; f++) {
            #pragma unroll
            for (int g = 0; g < 8; g++) {
                int row = bm + wm + f * 16 + (lane >> 2);
                int col = bn + wn + g * 8 + (lane & 3) * 2;
                float b0 = bias[col], b1 = bias[col + 1];
                float2 o0 = make_float2(acc[f][g][0] + b0, acc[f][g][1] + b1);
                float2 o1 = make_float2(acc[f][g][2] + b0, acc[f][g][3] + b1);
                *(float2*)(Cout + (size_t)row * GN + col)       = o0;
                *(float2*)(Cout + (size_t)(row + 8) * GN + col) = o1;
            }
        }
        __syncthreads();   // smem quiet before next tile's prologue load
    }
}

// ---------------------------------------------------------------------------
// Fused attention: grid (GCH, B*NH), block 256 (8 warps x 64 rows).
// Reads each q/k/v row once; does local attention AND global partials.
// ---------------------------------------------------------------------------
#define SCHUNK (S / GCH)   // 512
#define RPW (SCHUNK / 8)   // 64 rows per warp

__global__ __launch_bounds__(256) void gl_attn(
    const float* __restrict__ mask, float* __restrict__ out)
{
    const int ch = blockIdx.x;
    const int bh = blockIdx.y;
    const int b  = bh / NH;
    const int h  = bh % NH;

    __shared__ float sq0[D], sk0[D], sv0[D];
    __shared__ float gsc[SCHUNK];
    __shared__ float sp0[SCHUNK], sp1[SCHUNK];
    __shared__ float red[8];
    __shared__ float vwarp[8][D];

    const int tid  = threadIdx.x;
    const int lane = tid & 31;
    const int w    = tid >> 5;

    const size_t base0 = ((size_t)b * S) * H + (size_t)h * D;
    if (tid < D) {
        sq0[tid] = g_q[base0 + tid];
        sk0[tid] = g_k[base0 + tid];
        sv0[tid] = g_v[base0 + tid];
    }
    __syncthreads();

    const float q00 = sq0[2 * lane], q01 = sq0[2 * lane + 1];
    const float k00 = sk0[2 * lane], k01 = sk0[2 * lane + 1];
    const float v00 = sv0[2 * lane], v01 = sv0[2 * lane + 1];

    const int row0 = w * RPW;               // row within chunk
    const int s0   = ch * SCHUNK + row0;    // global s

    // ---- phase 1: scores (global + local), 2-way local softmax ----
    for (int i = 0; i < RPW; i++) {
        const int s = s0 + i;
        const size_t bs = ((size_t)b * S + s) * H + (size_t)h * D;
        float2 q2 = ((const float2*)(g_q + bs))[lane];
        float2 k2 = ((const float2*)(g_k + bs))[lane];

        float dg = q00 * k2.x + q01 * k2.y;   // gq . k_s
        float ds = q2.x * k2.x + q2.y * k2.y; // q_s . k_s
        float dl = q2.x * k00 + q2.y * k01;   // q_s . k_0
        #pragma unroll
        for (int o = 16; o; o >>= 1) {
            dg += __shfl_xor_sync(~0u, dg, o);
            ds += __shfl_xor_sync(~0u, ds, o);
            dl += __shfl_xor_sync(~0u, dl, o);
        }
        if (lane == 0) {
            gsc[row0 + i] = dg * SCALE + mask[(size_t)b * S + s];
            float ps = ds * SCALE, pg = dl * SCALE;
            float m  = fmaxf(ps, pg);
            float e0 = expf(ps - m), e1 = expf(pg - m);
            float inv = 1.f / (e0 + e1);
            sp0[row0 + i] = e0 * inv;
            sp1[row0 + i] = e1 * inv;
        }
    }
    __syncthreads();

    // ---- phase 2: block softmax stats for global scores ----
    float lm = fmaxf(gsc[tid], gsc[tid + 256]);
    #pragma unroll
    for (int o = 16; o; o >>= 1) lm = fmaxf(lm, __shfl_xor_sync(~0u, lm, o));
    if (lane == 0) red[w] = lm;
    __syncthreads();
    float bmax = red[0];
    #pragma unroll
    for (int ww = 1; ww < 8; ww++) bmax = fmaxf(bmax, red[ww]);
    __syncthreads();

    float e0 = expf(gsc[tid] - bmax);
    float e1 = expf(gsc[tid + 256] - bmax);
    gsc[tid] = e0; gsc[tid + 256] = e1;
    float ls = e0 + e1;
    #pragma unroll
    for (int o = 16; o; o >>= 1) ls += __shfl_xor_sync(~0u, ls, o);
    if (lane == 0) red[w] = ls;
    __syncthreads();
    float bsum = 0.f;
    #pragma unroll
    for (int ww = 0; ww < 8; ww++) bsum += red[ww];

    // ---- phase 3: V pass — local output + global V accumulation ----
    float a0 = 0.f, a1 = 0.f;
    for (int i = 0; i < RPW; i++) {
        const int s = s0 + i;
        const size_t bs = ((size_t)b * S + s) * H + (size_t)h * D;
        float2 v2 = ((const float2*)(g_v + bs))[lane];
        float pe = gsc[row0 + i];
        a0 = fmaf(pe, v2.x, a0);
        a1 = fmaf(pe, v2.y, a1);
        if (s != 0) {
            float p0 = sp0[row0 + i];
            float p1 = sp1[row0 + i];
            float2 o2 = make_float2(p0 * v2.x + p1 * v00,
                                    p0 * v2.y + p1 * v01);
            ((float2*)(out + bs))[lane] = o2;
            if (lane == 0) {
                size_t li = CTX_ELEMS + ((size_t)bh * (S - 1) + (s - 1)) * 2;
                out[li]     = p0;
                out[li + 1] = p1;
            }
        }
    }
    vwarp[w][2 * lane]     = a0;
    vwarp[w][2 * lane + 1] = a1;
    __syncthreads();

    if (tid < D) {
        float vs = 0.f;
        #pragma unroll
        for (int ww = 0; ww < 8; ww++) vs += vwarp[ww][tid];
        g_pvac[bh][ch][tid] = vs;
    }
    if (tid == 0) {
        g_pmax[bh][ch] = bmax;
        g_psum[bh][ch] = bsum;
    }
}

__global__ __launch_bounds__(64) void gattn_combine(float* __restrict__ out)
{
    const int bh = blockIdx.x;
    const int b  = bh / NH;
    const int h  = bh % NH;
    const int tid = threadIdx.x;

    float M = -INFINITY;
    #pragma unroll
    for (int c = 0; c < GCH; c++) M = fmaxf(M, g_pmax[bh][c]);
    float denom = 0.f, vs = 0.f;
    #pragma unroll
    for (int c = 0; c < GCH; c++) {
        float sc = expf(g_pmax[bh][c] - M);
        denom += g_psum[bh][c] * sc;
        vs    += g_pvac[bh][c][tid] * sc;
    }
    out[((size_t)b * S) * H + h * D + tid] = vs / denom;
}

// ---------------------------------------------------------------------------
extern "C" void kernel_launch(void* const* d_in, const int* in_sizes, int n_in,
                              void* d_out, int out_size)
{
    const float* hidden = (const float*)d_in[0];
    const float* mask   = (const float*)d_in[1];
    const float* Wq     = (const float*)d_in[2];
    const float* bq     = (const float*)d_in[3];
    const float* Wk     = (const float*)d_in[4];
    const float* bk     = (const float*)d_in[5];
    const float* Wv     = (const float*)d_in[6];
    const float* bv     = (const float*)d_in[7];
    float* out = (float*)d_out;

    split_all<<<(TOTN8 + 255) / 256, 256>>>(hidden, Wq, Wk, Wv);

    cudaFuncSetAttribute(qkv_gemm_mma, cudaFuncAttributeMaxDynamicSharedMemorySize, GSMEM);
    qkv_gemm_mma<<<GEMM_CTAS, 256, GSMEM>>>(bq, bk, bv);

    dim3 agrid(GCH, B * NH);
    gl_attn<<<agrid, 256>>>(mask, out);
    gattn_combine<<<B * NH, 64>>>(out);
}

// round 7
// speedup vs baseline: 1.3663x; 1.3663x over previous
#include <cuda_runtime.h>
#include <cuda_fp16.h>
#include <cuda_bf16.h>
#include <math.h>
#include <cstdint>

// ---------------------------------------------------------------------------
// Problem constants
// ---------------------------------------------------------------------------
#define B  4
#define S  4096
#define H  1024
#define NH 16
#define D  64
#define SCALE 0.125f

#define GM (B*S)   // 16384
#define GN H       // 1024
#define GK H       // 1024

#define CTX_ELEMS ((size_t)B * S * H)

// ---------------------------------------------------------------------------
// Device scratch (allocation-free)
// ---------------------------------------------------------------------------
__device__ float g_q[B * S * H];
__device__ float g_k[B * S * H];
__device__ float g_v[B * S * H];

__device__ __half g_ah[(size_t)GM * GK];        // hidden, fp16 (single term)
__device__ __half g_wh[3][(size_t)GN * GK];     // weights hi
__device__ __half g_wl[3][(size_t)GN * GK];     // weights lo

#define GCH 8
__device__ float g_pmax[B * NH][GCH];
__device__ float g_psum[B * NH][GCH];
__device__ float g_pvac[B * NH][GCH][D];

// ---------------------------------------------------------------------------
// Helpers
// ---------------------------------------------------------------------------
__device__ __forceinline__ uint32_t smem_u32(const void* p) {
    uint32_t a;
    asm("{ .reg .u64 t; cvta.to.shared.u64 t, %1; cvt.u32.u64 %0, t; }"
        : "=r"(a) : "l"(p));
    return a;
}

__device__ __forceinline__ void cp16(uint32_t dst, const void* src) {
    asm volatile("cp.async.cg.shared.global [%0], [%1], 16;"
                 :: "r"(dst), "l"(src));
}
#define CP_COMMIT() asm volatile("cp.async.commit_group;" ::: "memory")
#define CP_WAIT0()  asm volatile("cp.async.wait_group 0;" ::: "memory")
#define CP_WAIT1()  asm volatile("cp.async.wait_group 1;" ::: "memory")

__device__ __forceinline__ void ldsm4(uint32_t* r, uint32_t addr) {
    asm volatile("ldmatrix.sync.aligned.m8n8.x4.shared.b16 {%0,%1,%2,%3}, [%4];"
                 : "=r"(r[0]), "=r"(r[1]), "=r"(r[2]), "=r"(r[3]) : "r"(addr));
}

__device__ __forceinline__ void mma16816h(float* c, const uint32_t* a,
                                          uint32_t b0, uint32_t b1) {
    asm volatile(
        "mma.sync.aligned.m16n8k16.row.col.f32.f16.f16.f32 "
        "{%0,%1,%2,%3}, {%4,%5,%6,%7}, {%8,%9}, {%0,%1,%2,%3};"
        : "+f"(c[0]), "+f"(c[1]), "+f"(c[2]), "+f"(c[3])
        : "r"(a[0]), "r"(a[1]), "r"(a[2]), "r"(a[3]), "r"(b0), "r"(b1));
}

// ---------------------------------------------------------------------------
// Unified split: hidden -> fp16 (1 term); Wq/Wk/Wv -> fp16 hi+lo.
// ---------------------------------------------------------------------------
#define HN8 ((GM * GK) / 8)
#define WN8 ((GN * GK) / 8)
#define TOTN8 (HN8 + 3 * WN8)

__global__ __launch_bounds__(256) void split_all(
    const float* __restrict__ hidden,
    const float* __restrict__ Wq,
    const float* __restrict__ Wk,
    const float* __restrict__ Wv)
{
    int i = blockIdx.x * blockDim.x + threadIdx.x;
    if (i >= TOTN8) return;

    if (i < HN8) {
        size_t off = (size_t)i * 8;
        const float4* xp = (const float4*)(hidden + off);
        float4 a = xp[0], b = xp[1];
        float f[8] = {a.x, a.y, a.z, a.w, b.x, b.y, b.z, b.w};
        __align__(16) __half h[8];
        #pragma unroll
        for (int j = 0; j < 8; j++) h[j] = __float2half_rn(f[j]);
        *(uint4*)(g_ah + off) = *(uint4*)h;
    } else {
        int j0 = i - HN8;
        int w = j0 / WN8;
        size_t off = (size_t)(j0 - w * WN8) * 8;
        const float* src = (w == 0) ? Wq : (w == 1) ? Wk : Wv;
        const float4* xp = (const float4*)(src + off);
        float4 a = xp[0], b = xp[1];
        float f[8] = {a.x, a.y, a.z, a.w, b.x, b.y, b.z, b.w};
        __align__(16) __half h[8];
        __align__(16) __half l[8];
        #pragma unroll
        for (int j = 0; j < 8; j++) {
            h[j] = __float2half_rn(f[j]);
            l[j] = __float2half_rn(f[j] - __half2float(h[j]));
        }
        *(uint4*)(g_wh[w] + off) = *(uint4*)h;
        *(uint4*)(g_wl[w] + off) = *(uint4*)l;
    }
}

// ---------------------------------------------------------------------------
// QKV GEMM via mma.sync fp16, 2-term (A * (Wh + Wl)), fp32 accum.
// Block tile 256(M) x 128(N), K-chunk 64, 2-stage cp.async (R5 structure).
// 8 warps, each 64x64 warp tile.
// ---------------------------------------------------------------------------
#define TM 256
#define TN 128
#define TK 64
#define NCHUNK (GK / TK)                 // 16
#define AT_B  (TM * TK * 2)              // 32768
#define BT_B  (TN * TK * 2)              // 16384
#define STAGE_B (AT_B + 2 * BT_B)        // 65536
#define OFF_A  0
#define OFF_BH AT_B
#define OFF_BL (AT_B + BT_B)
#define GSMEM  (2 * STAGE_B)             // 131072

__global__ __launch_bounds__(256, 1) void qkv_gemm_mma(
    const float* __restrict__ bias_q,
    const float* __restrict__ bias_k,
    const float* __restrict__ bias_v)
{
    extern __shared__ __align__(1024) char sb[];

    const int z  = blockIdx.z;
    const int bm = blockIdx.y * TM;
    const int bn = blockIdx.x * TN;

    const __half* Ah = g_ah;
    const __half* Bh = g_wh[z];
    const __half* Bl = g_wl[z];
    const float* bias = (z == 0) ? bias_q : (z == 1) ? bias_k : bias_v;
    float* Cout = (z == 0) ? g_q : (z == 1) ? g_k : g_v;

    const int tid  = threadIdx.x;
    const int wid  = tid >> 5;
    const int lane = tid & 31;
    const int wm   = (wid >> 1) * 64;   // 0,64,128,192
    const int wn   = (wid & 1) * 64;    // 0,64

    const uint32_t sbase = smem_u32(sb);

    auto load_chunk = [&](int c, int buf) {
        const int kc = c * TK;
        const uint32_t stage = sbase + buf * STAGE_B;
        // A: 256 rows x 64 cols fp16 -> 2048 cp16, 8 per thread
        {
            uint32_t dtile = stage + OFF_A;
            #pragma unroll
            for (int i = 0; i < 8; i++) {
                int idx = tid + i * 256;
                int row = idx >> 3;
                int v   = idx & 7;
                uint32_t off = (uint32_t)(row << 7) + (uint32_t)(v << 4);
                off ^= ((uint32_t)(row & 7) << 4);
                cp16(dtile + off, Ah + (size_t)(bm + row) * GK + kc + v * 8);
            }
        }
        // B hi + lo: 128 rows x 64 cols each -> 4 cp16/thread each
        #pragma unroll
        for (int half = 0; half < 2; half++) {
            const __half* src = half ? Bl : Bh;
            uint32_t dtile = stage + (half ? OFF_BL : OFF_BH);
            #pragma unroll
            for (int i = 0; i < 4; i++) {
                int idx = tid + i * 256;
                int row = idx >> 3;
                int v   = idx & 7;
                uint32_t off = (uint32_t)(row << 7) + (uint32_t)(v << 4);
                off ^= ((uint32_t)(row & 7) << 4);
                cp16(dtile + off, src + (size_t)(bn + row) * GK + kc + v * 8);
            }
        }
    };

    float acc[4][8][4];
    #pragma unroll
    for (int f = 0; f < 4; f++)
        #pragma unroll
        for (int g = 0; g < 8; g++)
            #pragma unroll
            for (int j = 0; j < 4; j++) acc[f][g][j] = 0.f;

    const int a_row_l = lane & 15;
    const int a_kb_l  = (lane >> 4) << 4;
    const int b_row_l = (lane & 7) + ((lane >> 4) << 3);
    const int b_kb_l  = ((lane >> 3) & 1) << 4;

    load_chunk(0, 0);
    CP_COMMIT();

    for (int c = 0; c < NCHUNK; c++) {
        const int buf = c & 1;
        if (c + 1 < NCHUNK) {
            load_chunk(c + 1, buf ^ 1);
            CP_COMMIT();
            CP_WAIT1();
        } else {
            CP_WAIT0();
        }
        __syncthreads();

        const uint32_t stage  = sbase + buf * STAGE_B;
        const uint32_t baseA  = stage + OFF_A;
        const uint32_t baseBh = stage + OFF_BH;
        const uint32_t baseBl = stage + OFF_BL;

        #pragma unroll
        for (int s = 0; s < 4; s++) {
            uint32_t aF[4][4], bH[4][4], bL[4][4];
            const uint32_t cbA = (uint32_t)(s * 32 + a_kb_l);
            const uint32_t cbB = (uint32_t)(s * 32 + b_kb_l);
            #pragma unroll
            for (int f = 0; f < 4; f++) {
                int row = wm + f * 16 + a_row_l;
                uint32_t off = (uint32_t)(row << 7) + (cbA ^ ((uint32_t)(row & 7) << 4));
                ldsm4(aF[f], baseA + off);
            }
            #pragma unroll
            for (int g16 = 0; g16 < 4; g16++) {
                int row = wn + g16 * 16 + b_row_l;
                uint32_t off = (uint32_t)(row << 7) + (cbB ^ ((uint32_t)(row & 7) << 4));
                ldsm4(bH[g16], baseBh + off);
                ldsm4(bL[g16], baseBl + off);
            }
            #pragma unroll
            for (int f = 0; f < 4; f++) {
                #pragma unroll
                for (int g16 = 0; g16 < 4; g16++) {
                    #pragma unroll
                    for (int p = 0; p < 2; p++) {
                        float* cc = acc[f][g16 * 2 + p];
                        mma16816h(cc, aF[f], bH[g16][2*p], bH[g16][2*p+1]);
                        mma16816h(cc, aF[f], bL[g16][2*p], bL[g16][2*p+1]);
                    }
                }
            }
        }
        __syncthreads();
    }

    // ---- epilogue: bias + fp32 store ----
    #pragma unroll
    for (int f = 0; f < 4; f++) {
        #pragma unroll
        for (int g = 0; g < 8; g++) {
            int row = bm + wm + f * 16 + (lane >> 2);
            int col = bn + wn + g * 8 + (lane & 3) * 2;
            float b0 = bias[col], b1 = bias[col + 1];
            float2 o0 = make_float2(acc[f][g][0] + b0, acc[f][g][1] + b1);
            float2 o1 = make_float2(acc[f][g][2] + b0, acc[f][g][3] + b1);
            *(float2*)(Cout + (size_t)row * GN + col)       = o0;
            *(float2*)(Cout + (size_t)(row + 8) * GN + col) = o1;
        }
    }
}

// ---------------------------------------------------------------------------
// Fused attention: grid (GCH, B*NH), block 256 (8 warps x 64 rows).
// Reads each q/k/v row once; local attention AND global partials.
// ---------------------------------------------------------------------------
#define SCHUNK (S / GCH)   // 512
#define RPW (SCHUNK / 8)   // 64 rows per warp

__global__ __launch_bounds__(256) void gl_attn(
    const float* __restrict__ mask, float* __restrict__ out)
{
    const int ch = blockIdx.x;
    const int bh = blockIdx.y;
    const int b  = bh / NH;
    const int h  = bh % NH;

    __shared__ float sq0[D], sk0[D], sv0[D];
    __shared__ float gsc[SCHUNK];
    __shared__ float sp0[SCHUNK], sp1[SCHUNK];
    __shared__ float red[8];
    __shared__ float vwarp[8][D];

    const int tid  = threadIdx.x;
    const int lane = tid & 31;
    const int w    = tid >> 5;

    const size_t base0 = ((size_t)b * S) * H + (size_t)h * D;
    if (tid < D) {
        sq0[tid] = g_q[base0 + tid];
        sk0[tid] = g_k[base0 + tid];
        sv0[tid] = g_v[base0 + tid];
    }
    __syncthreads();

    const float q00 = sq0[2 * lane], q01 = sq0[2 * lane + 1];
    const float k00 = sk0[2 * lane], k01 = sk0[2 * lane + 1];
    const float v00 = sv0[2 * lane], v01 = sv0[2 * lane + 1];

    const int row0 = w * RPW;
    const int s0   = ch * SCHUNK + row0;

    // phase 1: scores (global + local 2-way softmax)
    for (int i = 0; i < RPW; i++) {
        const int s = s0 + i;
        const size_t bs = ((size_t)b * S + s) * H + (size_t)h * D;
        float2 q2 = ((const float2*)(g_q + bs))[lane];
        float2 k2 = ((const float2*)(g_k + bs))[lane];

        float dg = q00 * k2.x + q01 * k2.y;
        float ds = q2.x * k2.x + q2.y * k2.y;
        float dl = q2.x * k00 + q2.y * k01;
        #pragma unroll
        for (int o = 16; o; o >>= 1) {
            dg += __shfl_xor_sync(~0u, dg, o);
            ds += __shfl_xor_sync(~0u, ds, o);
            dl += __shfl_xor_sync(~0u, dl, o);
        }
        if (lane == 0) {
            gsc[row0 + i] = dg * SCALE + mask[(size_t)b * S + s];
            float ps = ds * SCALE, pg = dl * SCALE;
            float m  = fmaxf(ps, pg);
            float e0 = expf(ps - m), e1 = expf(pg - m);
            float inv = 1.f / (e0 + e1);
            sp0[row0 + i] = e0 * inv;
            sp1[row0 + i] = e1 * inv;
        }
    }
    __syncthreads();

    // phase 2: block softmax stats for global scores
    float lm = fmaxf(gsc[tid], gsc[tid + 256]);
    #pragma unroll
    for (int o = 16; o; o >>= 1) lm = fmaxf(lm, __shfl_xor_sync(~0u, lm, o));
    if (lane == 0) red[w] = lm;
    __syncthreads();
    float bmax = red[0];
    #pragma unroll
    for (int ww = 1; ww < 8; ww++) bmax = fmaxf(bmax, red[ww]);
    __syncthreads();

    float e0 = expf(gsc[tid] - bmax);
    float e1 = expf(gsc[tid + 256] - bmax);
    gsc[tid] = e0; gsc[tid + 256] = e1;
    float ls = e0 + e1;
    #pragma unroll
    for (int o = 16; o; o >>= 1) ls += __shfl_xor_sync(~0u, ls, o);
    if (lane == 0) red[w] = ls;
    __syncthreads();
    float bsum = 0.f;
    #pragma unroll
    for (int ww = 0; ww < 8; ww++) bsum += red[ww];

    // phase 3: V pass — local output + global V accumulation
    float a0 = 0.f, a1 = 0.f;
    for (int i = 0; i < RPW; i++) {
        const int s = s0 + i;
        const size_t bs = ((size_t)b * S + s) * H + (size_t)h * D;
        float2 v2 = ((const float2*)(g_v + bs))[lane];
        float pe = gsc[row0 + i];
        a0 = fmaf(pe, v2.x, a0);
        a1 = fmaf(pe, v2.y, a1);
        if (s != 0) {
            float p0 = sp0[row0 + i];
            float p1 = sp1[row0 + i];
            float2 o2 = make_float2(p0 * v2.x + p1 * v00,
                                    p0 * v2.y + p1 * v01);
            ((float2*)(out + bs))[lane] = o2;
            if (lane == 0) {
                size_t li = CTX_ELEMS + ((size_t)bh * (S - 1) + (s - 1)) * 2;
                out[li]     = p0;
                out[li + 1] = p1;
            }
        }
    }
    vwarp[w][2 * lane]     = a0;
    vwarp[w][2 * lane + 1] = a1;
    __syncthreads();

    if (tid < D) {
        float vs = 0.f;
        #pragma unroll
        for (int ww = 0; ww < 8; ww++) vs += vwarp[ww][tid];
        g_pvac[bh][ch][tid] = vs;
    }
    if (tid == 0) {
        g_pmax[bh][ch] = bmax;
        g_psum[bh][ch] = bsum;
    }
}

__global__ __launch_bounds__(64) void gattn_combine(float* __restrict__ out)
{
    const int bh = blockIdx.x;
    const int b  = bh / NH;
    const int h  = bh % NH;
    const int tid = threadIdx.x;

    float M = -INFINITY;
    #pragma unroll
    for (int c = 0; c < GCH; c++) M = fmaxf(M, g_pmax[bh][c]);
    float denom = 0.f, vs = 0.f;
    #pragma unroll
    for (int c = 0; c < GCH; c++) {
        float sc = expf(g_pmax[bh][c] - M);
        denom += g_psum[bh][c] * sc;
        vs    += g_pvac[bh][c][tid] * sc;
    }
    out[((size_t)b * S) * H + h * D + tid] = vs / denom;
}

// ---------------------------------------------------------------------------
extern "C" void kernel_launch(void* const* d_in, const int* in_sizes, int n_in,
                              void* d_out, int out_size)
{
    const float* hidden = (const float*)d_in[0];
    const float* mask   = (const float*)d_in[1];
    const float* Wq     = (const float*)d_in[2];
    const float* bq     = (const float*)d_in[3];
    const float* Wk     = (const float*)d_in[4];
    const float* bk     = (const float*)d_in[5];
    const float* Wv     = (const float*)d_in[6];
    const float* bv     = (const float*)d_in[7];
    float* out = (float*)d_out;

    split_all<<<(TOTN8 + 255) / 256, 256>>>(hidden, Wq, Wk, Wv);

    cudaFuncSetAttribute(qkv_gemm_mma, cudaFuncAttributeMaxDynamicSharedMemorySize, GSMEM);
    dim3 ggrid(GN / TN, GM / TM, 3);   // (8, 64, 3) = 1536 CTAs
    qkv_gemm_mma<<<ggrid, 256, GSMEM>>>(bq, bk, bv);

    dim3 agrid(GCH, B * NH);
    gl_attn<<<agrid, 256>>>(mask, out);
    gattn_combine<<<B * NH, 64>>>(out);
}

// round 8
// speedup vs baseline: 2.0316x; 1.4869x over previous
#include <cuda_runtime.h>
#include <cuda_fp16.h>
#include <math.h>
#include <cstdint>

// ---------------------------------------------------------------------------
// Problem constants
// ---------------------------------------------------------------------------
#define B  4
#define S  4096
#define H  1024
#define NH 16
#define D  64
#define SCALE 0.125f

#define GM (B*S)   // 16384
#define GN H       // 1024
#define GK H       // 1024

#define CTX_ELEMS ((size_t)B * S * H)

// ---------------------------------------------------------------------------
// Device scratch (allocation-free)
// ---------------------------------------------------------------------------
__device__ float g_q[B * S * H];
__device__ float g_k[B * S * H];
__device__ float g_v[B * S * H];

__device__ __half g_ah[(size_t)GM * GK];        // hidden, fp16
__device__ __half g_wh[3][(size_t)GN * GK];     // weights, fp16

#define GCH 8
__device__ float g_pmax[B * NH][GCH];
__device__ float g_psum[B * NH][GCH];
__device__ float g_pvac[B * NH][GCH][D];

// ---------------------------------------------------------------------------
// Helpers
// ---------------------------------------------------------------------------
__device__ __forceinline__ uint32_t smem_u32(const void* p) {
    uint32_t a;
    asm("{ .reg .u64 t; cvta.to.shared.u64 t, %1; cvt.u32.u64 %0, t; }"
        : "=r"(a) : "l"(p));
    return a;
}

__device__ __forceinline__ void cp16(uint32_t dst, const void* src) {
    asm volatile("cp.async.cg.shared.global [%0], [%1], 16;"
                 :: "r"(dst), "l"(src));
}
#define CP_COMMIT() asm volatile("cp.async.commit_group;" ::: "memory")
#define CP_WAIT0()  asm volatile("cp.async.wait_group 0;" ::: "memory")
#define CP_WAIT1()  asm volatile("cp.async.wait_group 1;" ::: "memory")

__device__ __forceinline__ void ldsm4(uint32_t* r, uint32_t addr) {
    asm volatile("ldmatrix.sync.aligned.m8n8.x4.shared.b16 {%0,%1,%2,%3}, [%4];"
                 : "=r"(r[0]), "=r"(r[1]), "=r"(r[2]), "=r"(r[3]) : "r"(addr));
}

__device__ __forceinline__ void mma16816h(float* c, const uint32_t* a,
                                          uint32_t b0, uint32_t b1) {
    asm volatile(
        "mma.sync.aligned.m16n8k16.row.col.f32.f16.f16.f32 "
        "{%0,%1,%2,%3}, {%4,%5,%6,%7}, {%8,%9}, {%0,%1,%2,%3};"
        : "+f"(c[0]), "+f"(c[1]), "+f"(c[2]), "+f"(c[3])
        : "r"(a[0]), "r"(a[1]), "r"(a[2]), "r"(a[3]), "r"(b0), "r"(b1));
}

// ---------------------------------------------------------------------------
// Unified convert: hidden + Wq/Wk/Wv -> fp16.
// ---------------------------------------------------------------------------
#define HN8 ((GM * GK) / 8)
#define WN8 ((GN * GK) / 8)
#define TOTN8 (HN8 + 3 * WN8)

__global__ __launch_bounds__(256) void split_all(
    const float* __restrict__ hidden,
    const float* __restrict__ Wq,
    const float* __restrict__ Wk,
    const float* __restrict__ Wv)
{
    int i = blockIdx.x * blockDim.x + threadIdx.x;
    if (i >= TOTN8) return;

    const float* src;
    __half* dst;
    size_t off;
    if (i < HN8) {
        src = hidden; dst = g_ah; off = (size_t)i * 8;
    } else {
        int j0 = i - HN8;
        int w = j0 / WN8;
        off = (size_t)(j0 - w * WN8) * 8;
        src = (w == 0) ? Wq : (w == 1) ? Wk : Wv;
        dst = g_wh[w];
    }

    const float4* xp = (const float4*)(src + off);
    float4 a = xp[0], b = xp[1];
    float f[8] = {a.x, a.y, a.z, a.w, b.x, b.y, b.z, b.w};
    __align__(16) __half h[8];
    #pragma unroll
    for (int j = 0; j < 8; j++) h[j] = __float2half_rn(f[j]);
    *(uint4*)(dst + off) = *(uint4*)h;
}

// ---------------------------------------------------------------------------
// QKV GEMM via mma.sync fp16 (single term), fp32 accum.
// Block tile 256(M) x 128(N), K-chunk 64, 2-stage cp.async.
// 8 warps, each 64x64 warp tile.
// ---------------------------------------------------------------------------
#define TM 256
#define TN 128
#define TK 64
#define NCHUNK (GK / TK)                 // 16
#define AT_B  (TM * TK * 2)              // 32768
#define BT_B  (TN * TK * 2)              // 16384
#define STAGE_B (AT_B + BT_B)            // 49152
#define OFF_A  0
#define OFF_BH AT_B
#define GSMEM  (2 * STAGE_B)             // 98304

__global__ __launch_bounds__(256, 1) void qkv_gemm_mma(
    const float* __restrict__ bias_q,
    const float* __restrict__ bias_k,
    const float* __restrict__ bias_v)
{
    extern __shared__ __align__(1024) char sb[];

    const int z  = blockIdx.z;
    const int bm = blockIdx.y * TM;
    const int bn = blockIdx.x * TN;

    const __half* Ah = g_ah;
    const __half* Bh = g_wh[z];
    const float* bias = (z == 0) ? bias_q : (z == 1) ? bias_k : bias_v;
    float* Cout = (z == 0) ? g_q : (z == 1) ? g_k : g_v;

    const int tid  = threadIdx.x;
    const int wid  = tid >> 5;
    const int lane = tid & 31;
    const int wm   = (wid >> 1) * 64;   // 0,64,128,192
    const int wn   = (wid & 1) * 64;    // 0,64

    const uint32_t sbase = smem_u32(sb);

    auto load_chunk = [&](int c, int buf) {
        const int kc = c * TK;
        const uint32_t stage = sbase + buf * STAGE_B;
        // A: 256 rows x 64 cols fp16 -> 8 cp16/thread
        {
            uint32_t dtile = stage + OFF_A;
            #pragma unroll
            for (int i = 0; i < 8; i++) {
                int idx = tid + i * 256;
                int row = idx >> 3;
                int v   = idx & 7;
                uint32_t off = (uint32_t)(row << 7) + (uint32_t)(v << 4);
                off ^= ((uint32_t)(row & 7) << 4);
                cp16(dtile + off, Ah + (size_t)(bm + row) * GK + kc + v * 8);
            }
        }
        // B: 128 rows x 64 cols -> 4 cp16/thread
        {
            uint32_t dtile = stage + OFF_BH;
            #pragma unroll
            for (int i = 0; i < 4; i++) {
                int idx = tid + i * 256;
                int row = idx >> 3;
                int v   = idx & 7;
                uint32_t off = (uint32_t)(row << 7) + (uint32_t)(v << 4);
                off ^= ((uint32_t)(row & 7) << 4);
                cp16(dtile + off, Bh + (size_t)(bn + row) * GK + kc + v * 8);
            }
        }
    };

    float acc[4][8][4];
    #pragma unroll
    for (int f = 0; f < 4; f++)
        #pragma unroll
        for (int g = 0; g < 8; g++)
            #pragma unroll
            for (int j = 0; j < 4; j++) acc[f][g][j] = 0.f;

    const int a_row_l = lane & 15;
    const int a_kb_l  = (lane >> 4) << 4;
    const int b_row_l = (lane & 7) + ((lane >> 4) << 3);
    const int b_kb_l  = ((lane >> 3) & 1) << 4;

    load_chunk(0, 0);
    CP_COMMIT();

    for (int c = 0; c < NCHUNK; c++) {
        const int buf = c & 1;
        if (c + 1 < NCHUNK) {
            load_chunk(c + 1, buf ^ 1);
            CP_COMMIT();
            CP_WAIT1();
        } else {
            CP_WAIT0();
        }
        __syncthreads();

        const uint32_t stage  = sbase + buf * STAGE_B;
        const uint32_t baseA  = stage + OFF_A;
        const uint32_t baseBh = stage + OFF_BH;

        #pragma unroll
        for (int s = 0; s < 4; s++) {
            uint32_t aF[4][4], bH[4][4];
            const uint32_t cbA = (uint32_t)(s * 32 + a_kb_l);
            const uint32_t cbB = (uint32_t)(s * 32 + b_kb_l);
            #pragma unroll
            for (int f = 0; f < 4; f++) {
                int row = wm + f * 16 + a_row_l;
                uint32_t off = (uint32_t)(row << 7) + (cbA ^ ((uint32_t)(row & 7) << 4));
                ldsm4(aF[f], baseA + off);
            }
            #pragma unroll
            for (int g16 = 0; g16 < 4; g16++) {
                int row = wn + g16 * 16 + b_row_l;
                uint32_t off = (uint32_t)(row << 7) + (cbB ^ ((uint32_t)(row & 7) << 4));
                ldsm4(bH[g16], baseBh + off);
            }
            #pragma unroll
            for (int f = 0; f < 4; f++) {
                #pragma unroll
                for (int g16 = 0; g16 < 4; g16++) {
                    #pragma unroll
                    for (int p = 0; p < 2; p++) {
                        float* cc = acc[f][g16 * 2 + p];
                        mma16816h(cc, aF[f], bH[g16][2*p], bH[g16][2*p+1]);
                    }
                }
            }
        }
        __syncthreads();
    }

    // ---- epilogue: bias + fp32 store ----
    #pragma unroll
    for (int f = 0; f < 4; f++) {
        #pragma unroll
        for (int g = 0; g < 8; g++) {
            int row = bm + wm + f * 16 + (lane >> 2);
            int col = bn + wn + g * 8 + (lane & 3) * 2;
            float b0 = bias[col], b1 = bias[col + 1];
            float2 o0 = make_float2(acc[f][g][0] + b0, acc[f][g][1] + b1);
            float2 o1 = make_float2(acc[f][g][2] + b0, acc[f][g][3] + b1);
            *(float2*)(Cout + (size_t)row * GN + col)       = o0;
            *(float2*)(Cout + (size_t)(row + 8) * GN + col) = o1;
        }
    }
}

// ---------------------------------------------------------------------------
// Fused attention: grid (GCH, B*NH), block 256 (8 warps x 64 rows).
// ---------------------------------------------------------------------------
#define SCHUNK (S / GCH)   // 512
#define RPW (SCHUNK / 8)   // 64 rows per warp

__global__ __launch_bounds__(256) void gl_attn(
    const float* __restrict__ mask, float* __restrict__ out)
{
    const int ch = blockIdx.x;
    const int bh = blockIdx.y;
    const int b  = bh / NH;
    const int h  = bh % NH;

    __shared__ float sq0[D], sk0[D], sv0[D];
    __shared__ float gsc[SCHUNK];
    __shared__ float sp0[SCHUNK], sp1[SCHUNK];
    __shared__ float red[8];
    __shared__ float vwarp[8][D];

    const int tid  = threadIdx.x;
    const int lane = tid & 31;
    const int w    = tid >> 5;

    const size_t base0 = ((size_t)b * S) * H + (size_t)h * D;
    if (tid < D) {
        sq0[tid] = g_q[base0 + tid];
        sk0[tid] = g_k[base0 + tid];
        sv0[tid] = g_v[base0 + tid];
    }
    __syncthreads();

    const float q00 = sq0[2 * lane], q01 = sq0[2 * lane + 1];
    const float k00 = sk0[2 * lane], k01 = sk0[2 * lane + 1];
    const float v00 = sv0[2 * lane], v01 = sv0[2 * lane + 1];

    const int row0 = w * RPW;
    const int s0   = ch * SCHUNK + row0;

    // phase 1: scores (global + local 2-way softmax)
    for (int i = 0; i < RPW; i++) {
        const int s = s0 + i;
        const size_t bs = ((size_t)b * S + s) * H + (size_t)h * D;
        float2 q2 = ((const float2*)(g_q + bs))[lane];
        float2 k2 = ((const float2*)(g_k + bs))[lane];

        float dg = q00 * k2.x + q01 * k2.y;
        float ds = q2.x * k2.x + q2.y * k2.y;
        float dl = q2.x * k00 + q2.y * k01;
        #pragma unroll
        for (int o = 16; o; o >>= 1) {
            dg += __shfl_xor_sync(~0u, dg, o);
            ds += __shfl_xor_sync(~0u, ds, o);
            dl += __shfl_xor_sync(~0u, dl, o);
        }
        if (lane == 0) {
            gsc[row0 + i] = dg * SCALE + mask[(size_t)b * S + s];
            float ps = ds * SCALE, pg = dl * SCALE;
            float m  = fmaxf(ps, pg);
            float e0 = expf(ps - m), e1 = expf(pg - m);
            float inv = 1.f / (e0 + e1);
            sp0[row0 + i] = e0 * inv;
            sp1[row0 + i] = e1 * inv;
        }
    }
    __syncthreads();

    // phase 2: block softmax stats for global scores
    float lm = fmaxf(gsc[tid], gsc[tid + 256]);
    #pragma unroll
    for (int o = 16; o; o >>= 1) lm = fmaxf(lm, __shfl_xor_sync(~0u, lm, o));
    if (lane == 0) red[w] = lm;
    __syncthreads();
    float bmax = red[0];
    #pragma unroll
    for (int ww = 1; ww < 8; ww++) bmax = fmaxf(bmax, red[ww]);
    __syncthreads();

    float e0 = expf(gsc[tid] - bmax);
    float e1 = expf(gsc[tid + 256] - bmax);
    gsc[tid] = e0; gsc[tid + 256] = e1;
    float ls = e0 + e1;
    #pragma unroll
    for (int o = 16; o; o >>= 1) ls += __shfl_xor_sync(~0u, ls, o);
    if (lane == 0) red[w] = ls;
    __syncthreads();
    float bsum = 0.f;
    #pragma unroll
    for (int ww = 0; ww < 8; ww++) bsum += red[ww];

    // phase 3: V pass — local output + global V accumulation
    float a0 = 0.f, a1 = 0.f;
    for (int i = 0; i < RPW; i++) {
        const int s = s0 + i;
        const size_t bs = ((size_t)b * S + s) * H + (size_t)h * D;
        float2 v2 = ((const float2*)(g_v + bs))[lane];
        float pe = gsc[row0 + i];
        a0 = fmaf(pe, v2.x, a0);
        a1 = fmaf(pe, v2.y, a1);
        if (s != 0) {
            float p0 = sp0[row0 + i];
            float p1 = sp1[row0 + i];
            float2 o2 = make_float2(p0 * v2.x + p1 * v00,
                                    p0 * v2.y + p1 * v01);
            ((float2*)(out + bs))[lane] = o2;
            if (lane == 0) {
                size_t li = CTX_ELEMS + ((size_t)bh * (S - 1) + (s - 1)) * 2;
                out[li]     = p0;
                out[li + 1] = p1;
            }
        }
    }
    vwarp[w][2 * lane]     = a0;
    vwarp[w][2 * lane + 1] = a1;
    __syncthreads();

    if (tid < D) {
        float vs = 0.f;
        #pragma unroll
        for (int ww = 0; ww < 8; ww++) vs += vwarp[ww][tid];
        g_pvac[bh][ch][tid] = vs;
    }
    if (tid == 0) {
        g_pmax[bh][ch] = bmax;
        g_psum[bh][ch] = bsum;
    }
}

__global__ __launch_bounds__(64) void gattn_combine(float* __restrict__ out)
{
    const int bh = blockIdx.x;
    const int b  = bh / NH;
    const int h  = bh % NH;
    const int tid = threadIdx.x;

    float M = -INFINITY;
    #pragma unroll
    for (int c = 0; c < GCH; c++) M = fmaxf(M, g_pmax[bh][c]);
    float denom = 0.f, vs = 0.f;
    #pragma unroll
    for (int c = 0; c < GCH; c++) {
        float sc = expf(g_pmax[bh][c] - M);
        denom += g_psum[bh][c] * sc;
        vs    += g_pvac[bh][c][tid] * sc;
    }
    out[((size_t)b * S) * H + h * D + tid] = vs / denom;
}

// ---------------------------------------------------------------------------
extern "C" void kernel_launch(void* const* d_in, const int* in_sizes, int n_in,
                              void* d_out, int out_size)
{
    const float* hidden = (const float*)d_in[0];
    const float* mask   = (const float*)d_in[1];
    const float* Wq     = (const float*)d_in[2];
    const float* bq     = (const float*)d_in[3];
    const float* Wk     = (const float*)d_in[4];
    const float* bk     = (const float*)d_in[5];
    const float* Wv     = (const float*)d_in[6];
    const float* bv     = (const float*)d_in[7];
    float* out = (float*)d_out;

    split_all<<<(TOTN8 + 255) / 256, 256>>>(hidden, Wq, Wk, Wv);

    cudaFuncSetAttribute(qkv_gemm_mma, cudaFuncAttributeMaxDynamicSharedMemorySize, GSMEM);
    dim3 ggrid(GN / TN, GM / TM, 3);   // (8, 64, 3) = 1536 CTAs
    qkv_gemm_mma<<<ggrid, 256, GSMEM>>>(bq, bk, bv);

    dim3 agrid(GCH, B * NH);
    gl_attn<<<agrid, 256>>>(mask, out);
    gattn_combine<<<B * NH, 64>>>(out);
}

// round 9
// speedup vs baseline: 2.1172x; 1.0422x over previous
#include <cuda_runtime.h>
#include <cuda_fp16.h>
#include <math.h>
#include <cstdint>

// ---------------------------------------------------------------------------
// Problem constants
// ---------------------------------------------------------------------------
#define B  4
#define S  4096
#define H  1024
#define NH 16
#define D  64
#define SCALE 0.125f

#define GM (B*S)   // 16384
#define GN H       // 1024
#define GK H       // 1024

#define CTX_ELEMS ((size_t)B * S * H)

// ---------------------------------------------------------------------------
// Device scratch (allocation-free)
// ---------------------------------------------------------------------------
__device__ __half g_q[B * S * H];     // q,k,v stored fp16
__device__ __half g_k[B * S * H];
__device__ __half g_v[B * S * H];

__device__ __half g_ah[(size_t)GM * GK];        // hidden, fp16
__device__ __half g_wh[3][(size_t)GN * GK];     // weights, fp16

#define GCH 8
__device__ float g_pmax[B * NH][GCH];
__device__ float g_psum[B * NH][GCH];
__device__ float g_pvac[B * NH][GCH][D];

// ---------------------------------------------------------------------------
// Helpers
// ---------------------------------------------------------------------------
__device__ __forceinline__ uint32_t smem_u32(const void* p) {
    uint32_t a;
    asm("{ .reg .u64 t; cvta.to.shared.u64 t, %1; cvt.u32.u64 %0, t; }"
        : "=r"(a) : "l"(p));
    return a;
}

__device__ __forceinline__ void cp16(uint32_t dst, const void* src) {
    asm volatile("cp.async.cg.shared.global [%0], [%1], 16;"
                 :: "r"(dst), "l"(src));
}
#define CP_COMMIT() asm volatile("cp.async.commit_group;" ::: "memory")
#define CP_WAIT0()  asm volatile("cp.async.wait_group 0;" ::: "memory")
#define CP_WAIT1()  asm volatile("cp.async.wait_group 1;" ::: "memory")

__device__ __forceinline__ void ldsm4(uint32_t* r, uint32_t addr) {
    asm volatile("ldmatrix.sync.aligned.m8n8.x4.shared.b16 {%0,%1,%2,%3}, [%4];"
                 : "=r"(r[0]), "=r"(r[1]), "=r"(r[2]), "=r"(r[3]) : "r"(addr));
}

__device__ __forceinline__ void mma16816h(float* c, const uint32_t* a,
                                          uint32_t b0, uint32_t b1) {
    asm volatile(
        "mma.sync.aligned.m16n8k16.row.col.f32.f16.f16.f32 "
        "{%0,%1,%2,%3}, {%4,%5,%6,%7}, {%8,%9}, {%0,%1,%2,%3};"
        : "+f"(c[0]), "+f"(c[1]), "+f"(c[2]), "+f"(c[3])
        : "r"(a[0]), "r"(a[1]), "r"(a[2]), "r"(a[3]), "r"(b0), "r"(b1));
}

// ---------------------------------------------------------------------------
// Unified convert: hidden + Wq/Wk/Wv -> fp16.
// ---------------------------------------------------------------------------
#define HN8 ((GM * GK) / 8)
#define WN8 ((GN * GK) / 8)
#define TOTN8 (HN8 + 3 * WN8)

__global__ __launch_bounds__(256) void split_all(
    const float* __restrict__ hidden,
    const float* __restrict__ Wq,
    const float* __restrict__ Wk,
    const float* __restrict__ Wv)
{
    int i = blockIdx.x * blockDim.x + threadIdx.x;
    if (i >= TOTN8) return;

    const float* src;
    __half* dst;
    size_t off;
    if (i < HN8) {
        src = hidden; dst = g_ah; off = (size_t)i * 8;
    } else {
        int j0 = i - HN8;
        int w = j0 / WN8;
        off = (size_t)(j0 - w * WN8) * 8;
        src = (w == 0) ? Wq : (w == 1) ? Wk : Wv;
        dst = g_wh[w];
    }

    const float4* xp = (const float4*)(src + off);
    float4 a = xp[0], b = xp[1];
    float f[8] = {a.x, a.y, a.z, a.w, b.x, b.y, b.z, b.w};
    __align__(16) __half h[8];
    #pragma unroll
    for (int j = 0; j < 8; j++) h[j] = __float2half_rn(f[j]);
    *(uint4*)(dst + off) = *(uint4*)h;
}

// ---------------------------------------------------------------------------
// QKV GEMM via mma.sync fp16, fp32 accum, fp16 output.
// Block tile 256(M) x 128(N), K-chunk 128 (two 64-col sub-tiles), 2-stage.
// 8 warps, each 64x64 warp tile.
// ---------------------------------------------------------------------------
#define TM 256
#define TN 128
#define TKC 128                            // K per chunk
#define NCHUNK (GK / TKC)                  // 8
#define AT_B  (TM * 64 * 2)                // 32768 per A sub-tile
#define BT_B  (TN * 64 * 2)                // 16384 per B sub-tile
#define OFF_A0 0
#define OFF_A1 AT_B
#define OFF_B0 (2 * AT_B)
#define OFF_B1 (2 * AT_B + BT_B)
#define STAGE_B (2 * AT_B + 2 * BT_B)      // 98304
#define GSMEM  (2 * STAGE_B)               // 196608

__global__ __launch_bounds__(256, 1) void qkv_gemm_mma(
    const float* __restrict__ bias_q,
    const float* __restrict__ bias_k,
    const float* __restrict__ bias_v)
{
    extern __shared__ __align__(1024) char sb[];

    const int z  = blockIdx.z;
    const int bm = blockIdx.y * TM;
    const int bn = blockIdx.x * TN;

    const __half* Ah = g_ah;
    const __half* Bh = g_wh[z];
    const float* bias = (z == 0) ? bias_q : (z == 1) ? bias_k : bias_v;
    __half* Cout = (z == 0) ? g_q : (z == 1) ? g_k : g_v;

    const int tid  = threadIdx.x;
    const int wid  = tid >> 5;
    const int lane = tid & 31;
    const int wm   = (wid >> 1) * 64;   // 0,64,128,192
    const int wn   = (wid & 1) * 64;    // 0,64

    const uint32_t sbase = smem_u32(sb);

    auto load_chunk = [&](int c, int buf) {
        const int kc = c * TKC;
        const uint32_t stage = sbase + buf * STAGE_B;
        // A sub-tiles: 256 rows x 64 cols each -> 8 cp16/thread each
        #pragma unroll
        for (int sub = 0; sub < 2; sub++) {
            uint32_t dtile = stage + (sub ? OFF_A1 : OFF_A0);
            const int kb = kc + sub * 64;
            #pragma unroll
            for (int i = 0; i < 8; i++) {
                int idx = tid + i * 256;
                int row = idx >> 3;
                int v   = idx & 7;
                uint32_t off = (uint32_t)(row << 7) + (uint32_t)(v << 4);
                off ^= ((uint32_t)(row & 7) << 4);
                cp16(dtile + off, Ah + (size_t)(bm + row) * GK + kb + v * 8);
            }
        }
        // B sub-tiles: 128 rows x 64 cols each -> 4 cp16/thread each
        #pragma unroll
        for (int sub = 0; sub < 2; sub++) {
            uint32_t dtile = stage + (sub ? OFF_B1 : OFF_B0);
            const int kb = kc + sub * 64;
            #pragma unroll
            for (int i = 0; i < 4; i++) {
                int idx = tid + i * 256;
                int row = idx >> 3;
                int v   = idx & 7;
                uint32_t off = (uint32_t)(row << 7) + (uint32_t)(v << 4);
                off ^= ((uint32_t)(row & 7) << 4);
                cp16(dtile + off, Bh + (size_t)(bn + row) * GK + kb + v * 8);
            }
        }
    };

    float acc[4][8][4];
    #pragma unroll
    for (int f = 0; f < 4; f++)
        #pragma unroll
        for (int g = 0; g < 8; g++)
            #pragma unroll
            for (int j = 0; j < 4; j++) acc[f][g][j] = 0.f;

    const int a_row_l = lane & 15;
    const int a_kb_l  = (lane >> 4) << 4;
    const int b_row_l = (lane & 7) + ((lane >> 4) << 3);
    const int b_kb_l  = ((lane >> 3) & 1) << 4;

    load_chunk(0, 0);
    CP_COMMIT();

    for (int c = 0; c < NCHUNK; c++) {
        const int buf = c & 1;
        if (c + 1 < NCHUNK) {
            load_chunk(c + 1, buf ^ 1);
            CP_COMMIT();
            CP_WAIT1();
        } else {
            CP_WAIT0();
        }
        __syncthreads();

        const uint32_t stage = sbase + buf * STAGE_B;

        #pragma unroll
        for (int sub = 0; sub < 2; sub++) {
            const uint32_t baseA = stage + (sub ? OFF_A1 : OFF_A0);
            const uint32_t baseB = stage + (sub ? OFF_B1 : OFF_B0);
            #pragma unroll
            for (int s = 0; s < 4; s++) {
                uint32_t aF[4][4], bH[4][4];
                const uint32_t cbA = (uint32_t)(s * 32 + a_kb_l);
                const uint32_t cbB = (uint32_t)(s * 32 + b_kb_l);
                #pragma unroll
                for (int f = 0; f < 4; f++) {
                    int row = wm + f * 16 + a_row_l;
                    uint32_t off = (uint32_t)(row << 7) + (cbA ^ ((uint32_t)(row & 7) << 4));
                    ldsm4(aF[f], baseA + off);
                }
                #pragma unroll
                for (int g16 = 0; g16 < 4; g16++) {
                    int row = wn + g16 * 16 + b_row_l;
                    uint32_t off = (uint32_t)(row << 7) + (cbB ^ ((uint32_t)(row & 7) << 4));
                    ldsm4(bH[g16], baseB + off);
                }
                #pragma unroll
                for (int f = 0; f < 4; f++) {
                    #pragma unroll
                    for (int g16 = 0; g16 < 4; g16++) {
                        #pragma unroll
                        for (int p = 0; p < 2; p++) {
                            float* cc = acc[f][g16 * 2 + p];
                            mma16816h(cc, aF[f], bH[g16][2*p], bH[g16][2*p+1]);
                        }
                    }
                }
            }
        }
        __syncthreads();
    }

    // ---- epilogue: bias + fp16 store ----
    #pragma unroll
    for (int f = 0; f < 4; f++) {
        #pragma unroll
        for (int g = 0; g < 8; g++) {
            int row = bm + wm + f * 16 + (lane >> 2);
            int col = bn + wn + g * 8 + (lane & 3) * 2;
            float b0 = bias[col], b1 = bias[col + 1];
            __half2 h0 = __floats2half2_rn(acc[f][g][0] + b0, acc[f][g][1] + b1);
            __half2 h1 = __floats2half2_rn(acc[f][g][2] + b0, acc[f][g][3] + b1);
            *(__half2*)(Cout + (size_t)row * GN + col)       = h0;
            *(__half2*)(Cout + (size_t)(row + 8) * GN + col) = h1;
        }
    }
}

// ---------------------------------------------------------------------------
// Fused attention: grid (GCH, B*NH), block 256 (8 warps x 64 rows).
// q/k/v read as fp16, all math in fp32.
// ---------------------------------------------------------------------------
#define SCHUNK (S / GCH)   // 512
#define RPW (SCHUNK / 8)   // 64 rows per warp

__global__ __launch_bounds__(256) void gl_attn(
    const float* __restrict__ mask, float* __restrict__ out)
{
    const int ch = blockIdx.x;
    const int bh = blockIdx.y;
    const int b  = bh / NH;
    const int h  = bh % NH;

    __shared__ float sq0[D], sk0[D], sv0[D];
    __shared__ float gsc[SCHUNK];
    __shared__ float sp0[SCHUNK], sp1[SCHUNK];
    __shared__ float red[8];
    __shared__ float vwarp[8][D];

    const int tid  = threadIdx.x;
    const int lane = tid & 31;
    const int w    = tid >> 5;

    const size_t base0 = ((size_t)b * S) * H + (size_t)h * D;
    if (tid < D) {
        sq0[tid] = __half2float(g_q[base0 + tid]);
        sk0[tid] = __half2float(g_k[base0 + tid]);
        sv0[tid] = __half2float(g_v[base0 + tid]);
    }
    __syncthreads();

    const float q00 = sq0[2 * lane], q01 = sq0[2 * lane + 1];
    const float k00 = sk0[2 * lane], k01 = sk0[2 * lane + 1];
    const float v00 = sv0[2 * lane], v01 = sv0[2 * lane + 1];

    const int row0 = w * RPW;
    const int s0   = ch * SCHUNK + row0;

    // phase 1: scores (global + local 2-way softmax)
    for (int i = 0; i < RPW; i++) {
        const int s = s0 + i;
        const size_t bs = ((size_t)b * S + s) * H + (size_t)h * D;
        float2 q2 = __half22float2(((const __half2*)(g_q + bs))[lane]);
        float2 k2 = __half22float2(((const __half2*)(g_k + bs))[lane]);

        float dg = q00 * k2.x + q01 * k2.y;
        float ds = q2.x * k2.x + q2.y * k2.y;
        float dl = q2.x * k00 + q2.y * k01;
        #pragma unroll
        for (int o = 16; o; o >>= 1) {
            dg += __shfl_xor_sync(~0u, dg, o);
            ds += __shfl_xor_sync(~0u, ds, o);
            dl += __shfl_xor_sync(~0u, dl, o);
        }
        if (lane == 0) {
            gsc[row0 + i] = dg * SCALE + mask[(size_t)b * S + s];
            float ps = ds * SCALE, pg = dl * SCALE;
            float m  = fmaxf(ps, pg);
            float e0 = expf(ps - m), e1 = expf(pg - m);
            float inv = 1.f / (e0 + e1);
            sp0[row0 + i] = e0 * inv;
            sp1[row0 + i] = e1 * inv;
        }
    }
    __syncthreads();

    // phase 2: block softmax stats for global scores
    float lm = fmaxf(gsc[tid], gsc[tid + 256]);
    #pragma unroll
    for (int o = 16; o; o >>= 1) lm = fmaxf(lm, __shfl_xor_sync(~0u, lm, o));
    if (lane == 0) red[w] = lm;
    __syncthreads();
    float bmax = red[0];
    #pragma unroll
    for (int ww = 1; ww < 8; ww++) bmax = fmaxf(bmax, red[ww]);
    __syncthreads();

    float e0 = expf(gsc[tid] - bmax);
    float e1 = expf(gsc[tid + 256] - bmax);
    gsc[tid] = e0; gsc[tid + 256] = e1;
    float ls = e0 + e1;
    #pragma unroll
    for (int o = 16; o; o >>= 1) ls += __shfl_xor_sync(~0u, ls, o);
    if (lane == 0) red[w] = ls;
    __syncthreads();
    float bsum = 0.f;
    #pragma unroll
    for (int ww = 0; ww < 8; ww++) bsum += red[ww];

    // phase 3: V pass — local output + global V accumulation
    float a0 = 0.f, a1 = 0.f;
    for (int i = 0; i < RPW; i++) {
        const int s = s0 + i;
        const size_t bs = ((size_t)b * S + s) * H + (size_t)h * D;
        float2 v2 = __half22float2(((const __half2*)(g_v + bs))[lane]);
        float pe = gsc[row0 + i];
        a0 = fmaf(pe, v2.x, a0);
        a1 = fmaf(pe, v2.y, a1);
        if (s != 0) {
            float p0 = sp0[row0 + i];
            float p1 = sp1[row0 + i];
            float2 o2 = make_float2(p0 * v2.x + p1 * v00,
                                    p0 * v2.y + p1 * v01);
            ((float2*)(out + bs))[lane] = o2;
            if (lane == 0) {
                size_t li = CTX_ELEMS + ((size_t)bh * (S - 1) + (s - 1)) * 2;
                out[li]     = p0;
                out[li + 1] = p1;
            }
        }
    }
    vwarp[w][2 * lane]     = a0;
    vwarp[w][2 * lane + 1] = a1;
    __syncthreads();

    if (tid < D) {
        float vs = 0.f;
        #pragma unroll
        for (int ww = 0; ww < 8; ww++) vs += vwarp[ww][tid];
        g_pvac[bh][ch][tid] = vs;
    }
    if (tid == 0) {
        g_pmax[bh][ch] = bmax;
        g_psum[bh][ch] = bsum;
    }
}

__global__ __launch_bounds__(64) void gattn_combine(float* __restrict__ out)
{
    const int bh = blockIdx.x;
    const int b  = bh / NH;
    const int h  = bh % NH;
    const int tid = threadIdx.x;

    float M = -INFINITY;
    #pragma unroll
    for (int c = 0; c < GCH; c++) M = fmaxf(M, g_pmax[bh][c]);
    float denom = 0.f, vs = 0.f;
    #pragma unroll
    for (int c = 0; c < GCH; c++) {
        float sc = expf(g_pmax[bh][c] - M);
        denom += g_psum[bh][c] * sc;
        vs    += g_pvac[bh][c][tid] * sc;
    }
    out[((size_t)b * S) * H + h * D + tid] = vs / denom;
}

// ---------------------------------------------------------------------------
extern "C" void kernel_launch(void* const* d_in, const int* in_sizes, int n_in,
                              void* d_out, int out_size)
{
    const float* hidden = (const float*)d_in[0];
    const float* mask   = (const float*)d_in[1];
    const float* Wq     = (const float*)d_in[2];
    const float* bq     = (const float*)d_in[3];
    const float* Wk     = (const float*)d_in[4];
    const float* bk     = (const float*)d_in[5];
    const float* Wv     = (const float*)d_in[6];
    const float* bv     = (const float*)d_in[7];
    float* out = (float*)d_out;

    split_all<<<(TOTN8 + 255) / 256, 256>>>(hidden, Wq, Wk, Wv);

    cudaFuncSetAttribute(qkv_gemm_mma, cudaFuncAttributeMaxDynamicSharedMemorySize, GSMEM);
    dim3 ggrid(GN / TN, GM / TM, 3);   // (8, 64, 3) = 1536 CTAs
    qkv_gemm_mma<<<ggrid, 256, GSMEM>>>(bq, bk, bv);

    dim3 agrid(GCH, B * NH);
    gl_attn<<<agrid, 256>>>(mask, out);
    gattn_combine<<<B * NH, 64>>>(out);
}

// round 10
// speedup vs baseline: 2.3412x; 1.1058x over previous
#include <cuda_runtime.h>
#include <cuda_fp16.h>
#include <math.h>
#include <cstdint>

// ---------------------------------------------------------------------------
// Problem constants
// ---------------------------------------------------------------------------
#define B  4
#define S  4096
#define H  1024
#define NH 16
#define D  64
#define SCALE 0.125f

#define GM (B*S)   // 16384
#define GN H       // 1024
#define GK H       // 1024

#define CTX_ELEMS ((size_t)B * S * H)

// ---------------------------------------------------------------------------
// Device scratch (allocation-free)
// ---------------------------------------------------------------------------
__device__ __half g_q[B * S * H];
__device__ __half g_k[B * S * H];
__device__ __half g_v[B * S * H];

__device__ __half g_ah[(size_t)GM * GK];
__device__ __half g_wh[3][(size_t)GN * GK];

#define GCH 16
__device__ float g_pmax[B * NH][GCH];
__device__ float g_psum[B * NH][GCH];
__device__ float g_pvac[B * NH][GCH][D];

// ---------------------------------------------------------------------------
// Helpers
// ---------------------------------------------------------------------------
__device__ __forceinline__ uint32_t smem_u32(const void* p) {
    uint32_t a;
    asm("{ .reg .u64 t; cvta.to.shared.u64 t, %1; cvt.u32.u64 %0, t; }"
        : "=r"(a) : "l"(p));
    return a;
}

__device__ __forceinline__ void cp16(uint32_t dst, const void* src) {
    asm volatile("cp.async.cg.shared.global [%0], [%1], 16;"
                 :: "r"(dst), "l"(src));
}
#define CP_COMMIT() asm volatile("cp.async.commit_group;" ::: "memory")
#define CP_WAIT0()  asm volatile("cp.async.wait_group 0;" ::: "memory")

__device__ __forceinline__ void ldsm4(uint32_t* r, uint32_t addr) {
    asm volatile("ldmatrix.sync.aligned.m8n8.x4.shared.b16 {%0,%1,%2,%3}, [%4];"
                 : "=r"(r[0]), "=r"(r[1]), "=r"(r[2]), "=r"(r[3]) : "r"(addr));
}

__device__ __forceinline__ void mma16816h(float* c, const uint32_t* a,
                                          uint32_t b0, uint32_t b1) {
    asm volatile(
        "mma.sync.aligned.m16n8k16.row.col.f32.f16.f16.f32 "
        "{%0,%1,%2,%3}, {%4,%5,%6,%7}, {%8,%9}, {%0,%1,%2,%3};"
        : "+f"(c[0]), "+f"(c[1]), "+f"(c[2]), "+f"(c[3])
        : "r"(a[0]), "r"(a[1]), "r"(a[2]), "r"(a[3]), "r"(b0), "r"(b1));
}

// ---------------------------------------------------------------------------
// Unified convert: hidden + Wq/Wk/Wv -> fp16.
// ---------------------------------------------------------------------------
#define HN8 ((GM * GK) / 8)
#define WN8 ((GN * GK) / 8)
#define TOTN8 (HN8 + 3 * WN8)

__global__ __launch_bounds__(256) void split_all(
    const float* __restrict__ hidden,
    const float* __restrict__ Wq,
    const float* __restrict__ Wk,
    const float* __restrict__ Wv)
{
    int i = blockIdx.x * blockDim.x + threadIdx.x;
    if (i >= TOTN8) return;

    const float* src;
    __half* dst;
    size_t off;
    if (i < HN8) {
        src = hidden; dst = g_ah; off = (size_t)i * 8;
    } else {
        int j0 = i - HN8;
        int w = j0 / WN8;
        off = (size_t)(j0 - w * WN8) * 8;
        src = (w == 0) ? Wq : (w == 1) ? Wk : Wv;
        dst = g_wh[w];
    }

    const float4* xp = (const float4*)(src + off);
    float4 a = xp[0], b = xp[1];
    float f[8] = {a.x, a.y, a.z, a.w, b.x, b.y, b.z, b.w};
    __align__(16) __half h[8];
    #pragma unroll
    for (int j = 0; j < 8; j++) h[j] = __float2half_rn(f[j]);
    *(uint4*)(dst + off) = *(uint4*)h;
}

// ---------------------------------------------------------------------------
// QKV GEMM via mma.sync fp16, fp32 accum, fp16 output.
// Block tile 256(M) x 128(N), K-chunk 128, 2-stage, ONE sync per chunk.
// ---------------------------------------------------------------------------
#define TM 256
#define TN 128
#define TKC 128
#define NCHUNK (GK / TKC)                  // 8
#define AT_B  (TM * 64 * 2)                // 32768 per A sub-tile
#define BT_B  (TN * 64 * 2)                // 16384 per B sub-tile
#define OFF_A0 0
#define OFF_A1 AT_B
#define OFF_B0 (2 * AT_B)
#define OFF_B1 (2 * AT_B + BT_B)
#define STAGE_B (2 * AT_B + 2 * BT_B)      // 98304
#define GSMEM  (2 * STAGE_B)               // 196608

__global__ __launch_bounds__(256, 1) void qkv_gemm_mma(
    const float* __restrict__ bias_q,
    const float* __restrict__ bias_k,
    const float* __restrict__ bias_v)
{
    extern __shared__ __align__(1024) char sb[];

    const int z  = blockIdx.z;
    const int bm = blockIdx.y * TM;
    const int bn = blockIdx.x * TN;

    const __half* Ah = g_ah;
    const __half* Bh = g_wh[z];
    const float* bias = (z == 0) ? bias_q : (z == 1) ? bias_k : bias_v;
    __half* Cout = (z == 0) ? g_q : (z == 1) ? g_k : g_v;

    const int tid  = threadIdx.x;
    const int wid  = tid >> 5;
    const int lane = tid & 31;
    const int wm   = (wid >> 1) * 64;
    const int wn   = (wid & 1) * 64;

    const uint32_t sbase = smem_u32(sb);

    auto load_chunk = [&](int c, int buf) {
        const int kc = c * TKC;
        const uint32_t stage = sbase + buf * STAGE_B;
        #pragma unroll
        for (int sub = 0; sub < 2; sub++) {
            uint32_t dtile = stage + (sub ? OFF_A1 : OFF_A0);
            const int kb = kc + sub * 64;
            #pragma unroll
            for (int i = 0; i < 8; i++) {
                int idx = tid + i * 256;
                int row = idx >> 3;
                int v   = idx & 7;
                uint32_t off = (uint32_t)(row << 7) + (uint32_t)(v << 4);
                off ^= ((uint32_t)(row & 7) << 4);
                cp16(dtile + off, Ah + (size_t)(bm + row) * GK + kb + v * 8);
            }
        }
        #pragma unroll
        for (int sub = 0; sub < 2; sub++) {
            uint32_t dtile = stage + (sub ? OFF_B1 : OFF_B0);
            const int kb = kc + sub * 64;
            #pragma unroll
            for (int i = 0; i < 4; i++) {
                int idx = tid + i * 256;
                int row = idx >> 3;
                int v   = idx & 7;
                uint32_t off = (uint32_t)(row << 7) + (uint32_t)(v << 4);
                off ^= ((uint32_t)(row & 7) << 4);
                cp16(dtile + off, Bh + (size_t)(bn + row) * GK + kb + v * 8);
            }
        }
    };

    float acc[4][8][4];
    #pragma unroll
    for (int f = 0; f < 4; f++)
        #pragma unroll
        for (int g = 0; g < 8; g++)
            #pragma unroll
            for (int j = 0; j < 4; j++) acc[f][g][j] = 0.f;

    const int a_row_l = lane & 15;
    const int a_kb_l  = (lane >> 4) << 4;
    const int b_row_l = (lane & 7) + ((lane >> 4) << 3);
    const int b_kb_l  = ((lane >> 3) & 1) << 4;

    load_chunk(0, 0);
    CP_COMMIT();

    for (int c = 0; c < NCHUNK; c++) {
        const int buf = c & 1;
        CP_WAIT0();          // chunk c landed (only group outstanding)
        __syncthreads();     // all copies visible; all warps done reading buf^1
        if (c + 1 < NCHUNK) {
            load_chunk(c + 1, buf ^ 1);
            CP_COMMIT();
        }

        const uint32_t stage = sbase + buf * STAGE_B;

        #pragma unroll
        for (int sub = 0; sub < 2; sub++) {
            const uint32_t baseA = stage + (sub ? OFF_A1 : OFF_A0);
            const uint32_t baseB = stage + (sub ? OFF_B1 : OFF_B0);
            #pragma unroll
            for (int s = 0; s < 4; s++) {
                uint32_t aF[4][4], bH[4][4];
                const uint32_t cbA = (uint32_t)(s * 32 + a_kb_l);
                const uint32_t cbB = (uint32_t)(s * 32 + b_kb_l);
                #pragma unroll
                for (int f = 0; f < 4; f++) {
                    int row = wm + f * 16 + a_row_l;
                    uint32_t off = (uint32_t)(row << 7) + (cbA ^ ((uint32_t)(row & 7) << 4));
                    ldsm4(aF[f], baseA + off);
                }
                #pragma unroll
                for (int g16 = 0; g16 < 4; g16++) {
                    int row = wn + g16 * 16 + b_row_l;
                    uint32_t off = (uint32_t)(row << 7) + (cbB ^ ((uint32_t)(row & 7) << 4));
                    ldsm4(bH[g16], baseB + off);
                }
                #pragma unroll
                for (int f = 0; f < 4; f++) {
                    #pragma unroll
                    for (int g16 = 0; g16 < 4; g16++) {
                        #pragma unroll
                        for (int p = 0; p < 2; p++) {
                            float* cc = acc[f][g16 * 2 + p];
                            mma16816h(cc, aF[f], bH[g16][2*p], bH[g16][2*p+1]);
                        }
                    }
                }
            }
        }
    }

    // ---- epilogue: bias + fp16 store ----
    #pragma unroll
    for (int f = 0; f < 4; f++) {
        #pragma unroll
        for (int g = 0; g < 8; g++) {
            int row = bm + wm + f * 16 + (lane >> 2);
            int col = bn + wn + g * 8 + (lane & 3) * 2;
            float b0 = bias[col], b1 = bias[col + 1];
            __half2 h0 = __floats2half2_rn(acc[f][g][0] + b0, acc[f][g][1] + b1);
            __half2 h1 = __floats2half2_rn(acc[f][g][2] + b0, acc[f][g][3] + b1);
            *(__half2*)(Cout + (size_t)row * GN + col)       = h0;
            *(__half2*)(Cout + (size_t)(row + 8) * GN + col) = h1;
        }
    }
}

// ---------------------------------------------------------------------------
// Fused attention: grid (GCH, B*NH), block 256 (8 warps x 32 rows).
// ---------------------------------------------------------------------------
#define SCHUNK (S / GCH)   // 256
#define RPW (SCHUNK / 8)   // 32 rows per warp

__global__ __launch_bounds__(256) void gl_attn(
    const float* __restrict__ mask, float* __restrict__ out)
{
    const int ch = blockIdx.x;
    const int bh = blockIdx.y;
    const int b  = bh / NH;
    const int h  = bh % NH;

    __shared__ float sq0[D], sk0[D], sv0[D];
    __shared__ float gsc[SCHUNK];
    __shared__ float sp0[SCHUNK], sp1[SCHUNK];
    __shared__ float red[8];
    __shared__ float vwarp[8][D];

    const int tid  = threadIdx.x;
    const int lane = tid & 31;
    const int w    = tid >> 5;

    const size_t base0 = ((size_t)b * S) * H + (size_t)h * D;
    if (tid < D) {
        sq0[tid] = __half2float(g_q[base0 + tid]);
        sk0[tid] = __half2float(g_k[base0 + tid]);
        sv0[tid] = __half2float(g_v[base0 + tid]);
    }
    __syncthreads();

    const float q00 = sq0[2 * lane], q01 = sq0[2 * lane + 1];
    const float k00 = sk0[2 * lane], k01 = sk0[2 * lane + 1];
    const float v00 = sv0[2 * lane], v01 = sv0[2 * lane + 1];

    const int row0 = w * RPW;
    const int s0   = ch * SCHUNK + row0;

    // phase 1: scores (global + local 2-way softmax)
    #pragma unroll 2
    for (int i = 0; i < RPW; i++) {
        const int s = s0 + i;
        const size_t bs = ((size_t)b * S + s) * H + (size_t)h * D;
        float2 q2 = __half22float2(((const __half2*)(g_q + bs))[lane]);
        float2 k2 = __half22float2(((const __half2*)(g_k + bs))[lane]);

        float dg = q00 * k2.x + q01 * k2.y;
        float ds = q2.x * k2.x + q2.y * k2.y;
        float dl = q2.x * k00 + q2.y * k01;
        #pragma unroll
        for (int o = 16; o; o >>= 1) {
            dg += __shfl_xor_sync(~0u, dg, o);
            ds += __shfl_xor_sync(~0u, ds, o);
            dl += __shfl_xor_sync(~0u, dl, o);
        }
        if (lane == 0) {
            gsc[row0 + i] = dg * SCALE + mask[(size_t)b * S + s];
            float ps = ds * SCALE, pg = dl * SCALE;
            float m  = fmaxf(ps, pg);
            float e0 = expf(ps - m), e1 = expf(pg - m);
            float inv = 1.f / (e0 + e1);
            sp0[row0 + i] = e0 * inv;
            sp1[row0 + i] = e1 * inv;
        }
    }
    __syncthreads();

    // phase 2: block softmax stats over SCHUNK=256 scores
    float lm = gsc[tid];
    #pragma unroll
    for (int o = 16; o; o >>= 1) lm = fmaxf(lm, __shfl_xor_sync(~0u, lm, o));
    if (lane == 0) red[w] = lm;
    __syncthreads();
    float bmax = red[0];
    #pragma unroll
    for (int ww = 1; ww < 8; ww++) bmax = fmaxf(bmax, red[ww]);
    __syncthreads();

    float e0 = expf(gsc[tid] - bmax);
    gsc[tid] = e0;
    float ls = e0;
    #pragma unroll
    for (int o = 16; o; o >>= 1) ls += __shfl_xor_sync(~0u, ls, o);
    if (lane == 0) red[w] = ls;
    __syncthreads();
    float bsum = 0.f;
    #pragma unroll
    for (int ww = 0; ww < 8; ww++) bsum += red[ww];

    // phase 3: V pass — local output + global V accumulation
    float a0 = 0.f, a1 = 0.f;
    #pragma unroll 2
    for (int i = 0; i < RPW; i++) {
        const int s = s0 + i;
        const size_t bs = ((size_t)b * S + s) * H + (size_t)h * D;
        float2 v2 = __half22float2(((const __half2*)(g_v + bs))[lane]);
        float pe = gsc[row0 + i];
        a0 = fmaf(pe, v2.x, a0);
        a1 = fmaf(pe, v2.y, a1);
        if (s != 0) {
            float p0 = sp0[row0 + i];
            float p1 = sp1[row0 + i];
            float2 o2 = make_float2(p0 * v2.x + p1 * v00,
                                    p0 * v2.y + p1 * v01);
            ((float2*)(out + bs))[lane] = o2;
            if (lane == 0) {
                size_t li = CTX_ELEMS + ((size_t)bh * (S - 1) + (s - 1)) * 2;
                out[li]     = p0;
                out[li + 1] = p1;
            }
        }
    }
    vwarp[w][2 * lane]     = a0;
    vwarp[w][2 * lane + 1] = a1;
    __syncthreads();

    if (tid < D) {
        float vs = 0.f;
        #pragma unroll
        for (int ww = 0; ww < 8; ww++) vs += vwarp[ww][tid];
        g_pvac[bh][ch][tid] = vs;
    }
    if (tid == 0) {
        g_pmax[bh][ch] = bmax;
        g_psum[bh][ch] = bsum;
    }
}

__global__ __launch_bounds__(64) void gattn_combine(float* __restrict__ out)
{
    const int bh = blockIdx.x;
    const int b  = bh / NH;
    const int h  = bh % NH;
    const int tid = threadIdx.x;

    float M = -INFINITY;
    #pragma unroll
    for (int c = 0; c < GCH; c++) M = fmaxf(M, g_pmax[bh][c]);
    float denom = 0.f, vs = 0.f;
    #pragma unroll
    for (int c = 0; c < GCH; c++) {
        float sc = expf(g_pmax[bh][c] - M);
        denom += g_psum[bh][c] * sc;
        vs    += g_pvac[bh][c][tid] * sc;
    }
    out[((size_t)b * S) * H + h * D + tid] = vs / denom;
}

// ---------------------------------------------------------------------------
extern "C" void kernel_launch(void* const* d_in, const int* in_sizes, int n_in,
                              void* d_out, int out_size)
{
    const float* hidden = (const float*)d_in[0];
    const float* mask   = (const float*)d_in[1];
    const float* Wq     = (const float*)d_in[2];
    const float* bq     = (const float*)d_in[3];
    const float* Wk     = (const float*)d_in[4];
    const float* bk     = (const float*)d_in[5];
    const float* Wv     = (const float*)d_in[6];
    const float* bv     = (const float*)d_in[7];
    float* out = (float*)d_out;

    split_all<<<(TOTN8 + 255) / 256, 256>>>(hidden, Wq, Wk, Wv);

    cudaFuncSetAttribute(qkv_gemm_mma, cudaFuncAttributeMaxDynamicSharedMemorySize, GSMEM);
    dim3 ggrid(GN / TN, GM / TM, 3);   // (8, 64, 3) = 1536 CTAs
    qkv_gemm_mma<<<ggrid, 256, GSMEM>>>(bq, bk, bv);

    dim3 agrid(GCH, B * NH);
    gl_attn<<<agrid, 256>>>(mask, out);
    gattn_combine<<<B * NH, 64>>>(out);
}